// round 15
// baseline (speedup 1.0000x reference)
#include <cuda_runtime.h>
#include <math.h>
#include <stdint.h>

#define B_TOT   4096
#define NSEQ    64
#define CDIM    192
#define NH      6
#define NW      64
#define CPBH    512
#define NTHREADS 384

// Shared memory (32-bit words), all XOR-swizzled, no padding:
//  sxb : u32[64][96] bf16-value pairs of x / attn-out, pairidx ^ ((row&7)<<2)
//  sal : u32[64][96] bf16-lo  pairs of x / attn-out,   pairidx ^ ((row&7)<<2)
//  squ/sku : u32[6*64][32] dual-bf16 q/k pairs (norm-scaled):
//            value pair pi at (pi ^ swg), lo pair at ((16|pi) ^ swg), swg=(row&7)<<2
//  sv    : f32[6*64][32], col ^ ((row&3)<<3)
#define SXB_OFF 0
#define SAL_OFF (SXB_OFF + 64*96)
#define SQ_OFF  (SAL_OFF + 64*96)
#define SK_OFF  (SQ_OFF + NH*64*32)
#define SV_OFF  (SK_OFF + NH*64*32)
#define SSC_OFF (SV_OFF + NH*64*32)
#define SMEM_WORDS (SSC_OFF + 8)
#define SMEM_BYTES (SMEM_WORDS * 4)

__device__ float g_bias[NH * NSEQ * NSEQ];
__device__ float g_bm[(size_t)NW * NH * NSEQ * NSEQ];

// Weight tables: (ng, ks16 0..11, nt, lane) -> uint4(bbf0, bbf1, blo0, blo1)
#define QKV_TBL (6*12*12*32)
#define PRJ_TBL (6*12*4*32)
__device__ uint4 g_wq[QKV_TBL];
__device__ uint4 g_wp[PRJ_TBL];

__device__ __forceinline__ uint32_t packbf(float hi, float lo) {
    uint32_t r; asm("cvt.rn.bf16x2.f32 %0, %1, %2;" : "=r"(r) : "f"(hi), "f"(lo)); return r;
}
__device__ __forceinline__ float bflo(uint32_t u) { return __uint_as_float(u << 16); }
__device__ __forceinline__ float bfhi(uint32_t u) { return __uint_as_float(u & 0xffff0000u); }
__device__ __forceinline__ void mma16bf(float* d, const uint32_t* a, uint32_t b0, uint32_t b1) {
    asm volatile("mma.sync.aligned.m16n8k16.row.col.f32.bf16.bf16.f32 "
                 "{%0,%1,%2,%3},{%4,%5,%6,%7},{%8,%9},{%0,%1,%2,%3};"
                 : "+f"(d[0]), "+f"(d[1]), "+f"(d[2]), "+f"(d[3])
                 : "r"(a[0]), "r"(a[1]), "r"(a[2]), "r"(a[3]), "r"(b0), "r"(b1));
}

// ---------------------------------------------------------------------------
// Kernel 0: weight tables in dual-bf16 fragment order (per k16 step).
// ---------------------------------------------------------------------------
__global__ void prep_w_kernel(const float* __restrict__ qkv_w,
                              const float* __restrict__ proj_w)
{
    int i = blockIdx.x * blockDim.x + threadIdx.x;
    const float* w; uint4* dst; int NT, idx;
    if (i < QKV_TBL)                { w = qkv_w;  dst = g_wq; NT = 12; idx = i; }
    else if (i < QKV_TBL + PRJ_TBL) { w = proj_w; dst = g_wp; NT = 4;  idx = i - QKV_TBL; }
    else return;

    int lane = idx & 31, r = idx >> 5;
    int nt = r % NT; r /= NT;
    int ks = r % 12; int ng = r / 12;
    int g = lane >> 2, qd = lane & 3;
    int col = ng * (NT * 8) + nt * 8 + g;
    const float* wr = &w[col * 192 + ks * 16];

    float e0 = wr[2 * qd],     e1 = wr[2 * qd + 1];
    float e8 = wr[2 * qd + 8], e9 = wr[2 * qd + 9];
    uint32_t b0 = packbf(e1, e0);
    uint32_t b1 = packbf(e9, e8);
    uint32_t l0 = packbf(e1 - bfhi(b0), e0 - bflo(b0));
    uint32_t l1 = packbf(e9 - bfhi(b1), e8 - bflo(b1));
    dst[idx] = make_uint4(b0, b1, l0, l1);
}

// ---------------------------------------------------------------------------
__global__ void cpb_kernel(const float* __restrict__ w1,
                           const float* __restrict__ b1,
                           const float* __restrict__ w2)
{
    __shared__ float rpb[225 * NH];
    const int t = threadIdx.x;
    const float inv_log2_8 = 1.0f / 3.0f;

    for (int e = t; e < 225 * NH; e += 256) {
        int te = e / NH, h = e % NH;
        int i = te / 15, j = te % 15;
        float cy = (float)(i - 7) * (8.0f / 7.0f);
        float cx = (float)(j - 7) * (8.0f / 7.0f);
        cy = copysignf(log2f(fabsf(cy) + 1.0f), cy) * inv_log2_8;
        cx = copysignf(log2f(fabsf(cx) + 1.0f), cx) * inv_log2_8;
        float acc = 0.0f;
        for (int k = 0; k < CPBH; k++) {
            float hm = fmaxf(cy * w1[2 * k] + cx * w1[2 * k + 1] + b1[k], 0.0f);
            acc += hm * w2[h * CPBH + k];
        }
        rpb[te * NH + h] = acc;
    }
    __syncthreads();

    for (int e = t; e < NH * NSEQ * NSEQ; e += 256) {
        int h = e / (NSEQ * NSEQ);
        int rr = e % (NSEQ * NSEQ);
        int i = rr / NSEQ, j = rr % NSEQ;
        int dy = (i >> 3) - (j >> 3) + 7;
        int dx = (i & 7) - (j & 7) + 7;
        g_bias[e] = 16.0f / (1.0f + expf(-rpb[(dy * 15 + dx) * NH + h]));
    }
}

__global__ void bm_kernel(const float* __restrict__ mask)
{
    int blk = blockIdx.x;            // widx*NH + h
    int widx = blk / NH, h = blk % NH;
    const float* mrow = mask + (size_t)widx * NSEQ * NSEQ;
    const float* brow = g_bias + h * NSEQ * NSEQ;
    float* dst = g_bm + (size_t)blk * NSEQ * NSEQ;
    for (int i = threadIdx.x; i < NSEQ * NSEQ; i += 256)
        dst[i] = brow[i] + mrow[i];
}

// ---------------------------------------------------------------------------
__global__ __launch_bounds__(NTHREADS)
void win_attn_kernel(const float* __restrict__ x,
                     const float* __restrict__ q_bias,
                     const float* __restrict__ v_bias,
                     const float* __restrict__ logit_scale,
                     const float* __restrict__ proj_b,
                     float* __restrict__ out)
{
    extern __shared__ float sm[];
    uint32_t* sxb = (uint32_t*)(sm + SXB_OFF);
    uint32_t* sal = (uint32_t*)(sm + SAL_OFF);
    uint32_t* squ = (uint32_t*)(sm + SQ_OFF);
    uint32_t* sku = (uint32_t*)(sm + SK_OFF);
    float*    sv  = sm + SV_OFF;
    float*    sscale = sm + SSC_OFF;

    const int t = threadIdx.x;
    const int b = blockIdx.x;
    const int widx = b & (NW - 1);
    const float* xb = x + (size_t)b * NSEQ * CDIM;

    const int w    = t >> 5;
    const int lane = t & 31;
    const int g    = lane >> 2;
    const int qd   = lane & 3;
    const int swg  = g << 2;

    // -------- load x as dual-bf16 pairs (swizzled) --------
    for (int idx = t; idx < NSEQ * CDIM / 4; idx += NTHREADS) {
        float4 v4 = ((const float4*)xb)[idx];
        int n = (idx * 4) / CDIM;
        int p = ((idx * 4) % CDIM) >> 1;     // even pair index
        int sw = (n & 7) << 2;
        uint32_t b0 = packbf(v4.y, v4.x);
        uint32_t b1 = packbf(v4.w, v4.z);
        uint32_t l0 = packbf(v4.y - bfhi(b0), v4.x - bflo(b0));
        uint32_t l1 = packbf(v4.w - bfhi(b1), v4.z - bflo(b1));
        *(uint2*)&sxb[n * 96 + (p ^ sw)] = make_uint2(b0, b1);
        *(uint2*)&sal[n * 96 + (p ^ sw)] = make_uint2(l0, l1);
    }
    if (t < NH) sscale[t] = __expf(fminf(logit_scale[t], 4.60517019f)); // ln(100)
    __syncthreads();

    // ============ Phase 1: QKV GEMM (dual-bf16, 3 mma per k16) ============
    {
        const int mg = w & 1;
        const int ng = w >> 1;

        float acc[2][12][4];
        #pragma unroll
        for (int a = 0; a < 2; a++)
            #pragma unroll
            for (int nt = 0; nt < 12; nt++)
                #pragma unroll
                for (int e = 0; e < 4; e++) acc[a][nt][e] = 0.0f;

        const uint4* wtab = &g_wq[(ng * 12 * 12) * 32 + lane];

        #pragma unroll 2
        for (int ks = 0; ks < 12; ks++) {
            int c0 = 8 * ks;
            int i0 = (c0 + qd) ^ swg, i1 = (c0 + 4 + qd) ^ swg;
            uint32_t ab[2][4], al[2][4];
            #pragma unroll
            for (int mt = 0; mt < 2; mt++) {
                int r0 = mg * 32 + mt * 16 + g;
                const uint32_t* B0 = &sxb[r0 * 96];
                const uint32_t* B8 = B0 + 8 * 96;
                const uint32_t* L0 = &sal[r0 * 96];
                const uint32_t* L8 = L0 + 8 * 96;
                ab[mt][0] = B0[i0]; ab[mt][1] = B8[i0];
                ab[mt][2] = B0[i1]; ab[mt][3] = B8[i1];
                al[mt][0] = L0[i0]; al[mt][1] = L8[i0];
                al[mt][2] = L0[i1]; al[mt][3] = L8[i1];
            }
            const uint4* wrow = wtab + (ks * 12) * 32;
            #pragma unroll
            for (int nt = 0; nt < 12; nt++) {
                uint4 bb = wrow[nt * 32];
                #pragma unroll
                for (int mt = 0; mt < 2; mt++) {
                    mma16bf(acc[mt][nt], ab[mt], bb.x, bb.y);
                    mma16bf(acc[mt][nt], al[mt], bb.x, bb.y);
                    mma16bf(acc[mt][nt], ab[mt], bb.z, bb.w);
                }
            }
        }

        // ---- norms (q,k) then scatter with folded scales ----
        const int s = ng >> 1;   // 0=q, 1=k, 2=v
        float inv[2][2][3];
        if (s < 2) {
            float ssq[2][2][3];
            #pragma unroll
            for (int a = 0; a < 2; a++)
                #pragma unroll
                for (int c = 0; c < 2; c++)
                    #pragma unroll
                    for (int hh = 0; hh < 3; hh++) ssq[a][c][hh] = 0.0f;
            #pragma unroll
            for (int mt = 0; mt < 2; mt++)
                #pragma unroll
                for (int nt = 0; nt < 12; nt++) {
                    int rem = ng * 96 + nt * 8 + qd * 2 - s * 192;
                    #pragma unroll
                    for (int rr = 0; rr < 2; rr++) {
                        float v0 = acc[mt][nt][rr * 2 + 0];
                        float v1 = acc[mt][nt][rr * 2 + 1];
                        if (s == 0) { v0 += q_bias[rem]; v1 += q_bias[rem + 1]; }
                        ssq[mt][rr][nt >> 2] += v0 * v0 + v1 * v1;
                    }
                }
            #pragma unroll
            for (int mt = 0; mt < 2; mt++)
                #pragma unroll
                for (int rr = 0; rr < 2; rr++)
                    #pragma unroll
                    for (int hs = 0; hs < 3; hs++) {
                        float tot = ssq[mt][rr][hs];
                        tot += __shfl_xor_sync(0xffffffffu, tot, 1);
                        tot += __shfl_xor_sync(0xffffffffu, tot, 2);
                        float sc = (s == 0) ? sscale[(ng & 1) * 3 + hs] : 1.0f;
                        inv[mt][rr][hs] = sc / fmaxf(sqrtf(tot), 1e-12f);
                    }
        }

        #pragma unroll
        for (int mt = 0; mt < 2; mt++) {
            #pragma unroll
            for (int nt = 0; nt < 12; nt++) {
                int rem = ng * 96 + nt * 8 + qd * 2 - s * 192;
                int h = rem >> 5, d = rem & 31;
                int pi = d >> 1;
                #pragma unroll
                for (int rr = 0; rr < 2; rr++) {
                    int n = mg * 32 + mt * 16 + g + rr * 8;
                    float v0 = acc[mt][nt][rr * 2 + 0];
                    float v1 = acc[mt][nt][rr * 2 + 1];
                    if (s < 2) {
                        float iv = inv[mt][rr][nt >> 2];
                        float w0, w1;
                        if (s == 0) { w0 = (v0 + q_bias[rem]) * iv; w1 = (v1 + q_bias[rem + 1]) * iv; }
                        else        { w0 = v0 * iv; w1 = v1 * iv; }
                        uint32_t ub = packbf(w1, w0);
                        uint32_t ul = packbf(w1 - bfhi(ub), w0 - bflo(ub));
                        uint32_t* dstp = (s == 0) ? squ : sku;
                        int row = h * 64 + n;
                        dstp[row * 32 + (pi ^ swg)] = ub;
                        dstp[row * 32 + ((16 | pi) ^ swg)] = ul;
                    } else {
                        *(float2*)&sv[(h * 64 + n) * 32 + (d ^ ((g & 3) << 3))] =
                            make_float2(v0 + v_bias[rem], v1 + v_bias[rem + 1]);
                    }
                }
            }
        }
    }
    __syncthreads();

    // ============ Phase 2: attention (dual-bf16 S, dual-bf16 PV) ============
    {
        const int h  = w >> 1;
        const int m0 = (w & 1) * 32;

        float p[2][8][4];
        #pragma unroll
        for (int mt = 0; mt < 2; mt++)
            #pragma unroll
            for (int nt = 0; nt < 8; nt++)
                #pragma unroll
                for (int e = 0; e < 4; e++) p[mt][nt][e] = 0.0f;

        // ---- preload all q fragments (value + lo) for both k16 halves ----
        uint32_t aqb[2][2][4], aql[2][2][4];   // [u][mt][4]
        #pragma unroll
        for (int u = 0; u < 2; u++) {
            int c0 = (8 * u + qd) ^ swg;
            int c1 = (8 * u + 4 + qd) ^ swg;
            int c2 = (16 | (8 * u + qd)) ^ swg;
            int c3 = (16 | (8 * u + 4 + qd)) ^ swg;
            #pragma unroll
            for (int mt = 0; mt < 2; mt++) {
                const uint32_t* Q0 = &squ[(h * 64 + m0 + mt * 16 + g) * 32];
                const uint32_t* Q8 = Q0 + 8 * 32;
                aqb[u][mt][0] = Q0[c0]; aqb[u][mt][1] = Q8[c0];
                aqb[u][mt][2] = Q0[c1]; aqb[u][mt][3] = Q8[c1];
                aql[u][mt][0] = Q0[c2]; aql[u][mt][1] = Q8[c2];
                aql[u][mt][2] = Q0[c3]; aql[u][mt][3] = Q8[c3];
            }
        }

        #pragma unroll
        for (int u = 0; u < 2; u++) {
            int c0 = (8 * u + qd) ^ swg;
            int c1 = (8 * u + 4 + qd) ^ swg;
            int c2 = (16 | (8 * u + qd)) ^ swg;
            int c3 = (16 | (8 * u + 4 + qd)) ^ swg;
            #pragma unroll
            for (int nt = 0; nt < 8; nt++) {
                const uint32_t* K0 = &sku[(h * 64 + nt * 8 + g) * 32];
                uint32_t kb0 = K0[c0], kb1 = K0[c1];
                uint32_t kl0 = K0[c2], kl1 = K0[c3];
                #pragma unroll
                for (int mt = 0; mt < 2; mt++) {
                    mma16bf(p[mt][nt], aqb[u][mt], kb0, kb1);
                    mma16bf(p[mt][nt], aql[u][mt], kb0, kb1);
                    mma16bf(p[mt][nt], aqb[u][mt], kl0, kl1);
                }
            }
        }

        // ---- bias+mask + exp (no max pass: |S| <= ~35, fp32-safe);
        //      normalization deferred to after PV (linear) ----
        const float* bmb = &g_bm[((size_t)widx * NH + h) * NSEQ * NSEQ];
        float rsn[2][2];
        #pragma unroll
        for (int mt = 0; mt < 2; mt++) {
            #pragma unroll
            for (int r2 = 0; r2 < 2; r2++) {
                int row = m0 + mt * 16 + g + 8 * r2;
                const float* bmr = bmb + row * 64 + qd * 2;
                float sum = 0.0f;
                #pragma unroll
                for (int nt = 0; nt < 8; nt++) {
                    float2 bmv = *(const float2*)&bmr[nt * 8];
                    float e0 = __expf(p[mt][nt][r2 * 2 + 0] + bmv.x);
                    float e1 = __expf(p[mt][nt][r2 * 2 + 1] + bmv.y);
                    p[mt][nt][r2 * 2 + 0] = e0;
                    p[mt][nt][r2 * 2 + 1] = e1;
                    sum += e0 + e1;
                }
                sum += __shfl_xor_sync(0xffffffffu, sum, 1);
                sum += __shfl_xor_sync(0xffffffffu, sum, 2);
                rsn[mt][r2] = 1.0f / sum;
            }
        }

        // ---- PV: dual-bf16 mma, P packed directly from S accumulators ----
        float o[2][4][4];
        #pragma unroll
        for (int mt = 0; mt < 2; mt++)
            #pragma unroll
            for (int nt = 0; nt < 4; nt++)
                #pragma unroll
                for (int e = 0; e < 4; e++) o[mt][nt][e] = 0.0f;

        #pragma unroll
        for (int u = 0; u < 4; u++) {
            uint32_t Ab[2][4], Al[2][4];
            #pragma unroll
            for (int mt = 0; mt < 2; mt++) {
                float p00 = p[mt][2*u][0],   p01 = p[mt][2*u][1];
                float p02 = p[mt][2*u][2],   p03 = p[mt][2*u][3];
                float p10 = p[mt][2*u+1][0], p11 = p[mt][2*u+1][1];
                float p12 = p[mt][2*u+1][2], p13 = p[mt][2*u+1][3];
                Ab[mt][0] = packbf(p01, p00);
                Ab[mt][1] = packbf(p03, p02);
                Ab[mt][2] = packbf(p11, p10);
                Ab[mt][3] = packbf(p13, p12);
                Al[mt][0] = packbf(p01 - bfhi(Ab[mt][0]), p00 - bflo(Ab[mt][0]));
                Al[mt][1] = packbf(p03 - bfhi(Ab[mt][1]), p02 - bflo(Ab[mt][1]));
                Al[mt][2] = packbf(p11 - bfhi(Ab[mt][2]), p10 - bflo(Ab[mt][2]));
                Al[mt][3] = packbf(p13 - bfhi(Ab[mt][3]), p12 - bflo(Ab[mt][3]));
            }
            int t0 = 16 * u + 2 * qd;
            int t1 = t0 + 8;
            #pragma unroll
            for (int nt = 0; nt < 4; nt++) {
                int d = nt * 8 + g;
                float v00 = sv[(h * 64 + t0) * 32     + (d ^ ((t0 & 3) << 3))];
                float v01 = sv[(h * 64 + t0 + 1) * 32 + (d ^ (((t0 + 1) & 3) << 3))];
                float v10 = sv[(h * 64 + t1) * 32     + (d ^ ((t1 & 3) << 3))];
                float v11 = sv[(h * 64 + t1 + 1) * 32 + (d ^ (((t1 + 1) & 3) << 3))];
                uint32_t B0 = packbf(v01, v00);
                uint32_t B1 = packbf(v11, v10);
                uint32_t L0 = packbf(v01 - bfhi(B0), v00 - bflo(B0));
                uint32_t L1 = packbf(v11 - bfhi(B1), v10 - bflo(B1));
                #pragma unroll
                for (int mt = 0; mt < 2; mt++) {
                    mma16bf(o[mt][nt], Ab[mt], B0, B1);
                    mma16bf(o[mt][nt], Al[mt], B0, B1);
                    mma16bf(o[mt][nt], Ab[mt], L0, L1);
                }
            }
        }

        // ---- write attn output (normalized here) as dual-bf16 pairs ----
        #pragma unroll
        for (int mt = 0; mt < 2; mt++) {
            #pragma unroll
            for (int nt = 0; nt < 4; nt++) {
                int pidx = h * 16 + nt * 4 + qd;       // pair index of col0
                #pragma unroll
                for (int r2 = 0; r2 < 2; r2++) {
                    int row = m0 + mt * 16 + g + 8 * r2;
                    float rs = rsn[mt][r2];
                    float o0 = o[mt][nt][r2 * 2 + 0] * rs;
                    float o1 = o[mt][nt][r2 * 2 + 1] * rs;
                    uint32_t ob = packbf(o1, o0);
                    uint32_t ol = packbf(o1 - bfhi(ob), o0 - bflo(ob));
                    sxb[row * 96 + (pidx ^ swg)] = ob;
                    sal[row * 96 + (pidx ^ swg)] = ol;
                }
            }
        }
    }
    __syncthreads();

    // ============ Phase 3: proj GEMM (dual-bf16, 3 mma per k16) ============
    {
        const int mg = w & 1;
        const int ng = w >> 1;

        float acc[2][4][4];
        #pragma unroll
        for (int a = 0; a < 2; a++)
            #pragma unroll
            for (int nt = 0; nt < 4; nt++)
                #pragma unroll
                for (int e = 0; e < 4; e++) acc[a][nt][e] = 0.0f;

        const uint4* wtab = &g_wp[(ng * 12 * 4) * 32 + lane];

        #pragma unroll 4
        for (int ks = 0; ks < 12; ks++) {
            int c0 = 8 * ks;
            int i0 = (c0 + qd) ^ swg, i1 = (c0 + 4 + qd) ^ swg;
            uint32_t ab[2][4], al[2][4];
            #pragma unroll
            for (int mt = 0; mt < 2; mt++) {
                int r0 = mg * 32 + mt * 16 + g;
                const uint32_t* B0 = &sxb[r0 * 96];
                const uint32_t* B8 = B0 + 8 * 96;
                const uint32_t* L0 = &sal[r0 * 96];
                const uint32_t* L8 = L0 + 8 * 96;
                ab[mt][0] = B0[i0]; ab[mt][1] = B8[i0];
                ab[mt][2] = B0[i1]; ab[mt][3] = B8[i1];
                al[mt][0] = L0[i0]; al[mt][1] = L8[i0];
                al[mt][2] = L0[i1]; al[mt][3] = L8[i1];
            }
            const uint4* wrow = wtab + (ks * 4) * 32;
            #pragma unroll
            for (int nt = 0; nt < 4; nt++) {
                uint4 bb = wrow[nt * 32];
                #pragma unroll
                for (int mt = 0; mt < 2; mt++) {
                    mma16bf(acc[mt][nt], ab[mt], bb.x, bb.y);
                    mma16bf(acc[mt][nt], al[mt], bb.x, bb.y);
                    mma16bf(acc[mt][nt], ab[mt], bb.z, bb.w);
                }
            }
        }

        float* ob = out + (size_t)b * NSEQ * CDIM;
        #pragma unroll
        for (int mt = 0; mt < 2; mt++) {
            #pragma unroll
            for (int nt = 0; nt < 4; nt++) {
                int col0 = ng * 32 + nt * 8 + qd * 2;
                float pb0 = proj_b[col0], pb1 = proj_b[col0 + 1];
                #pragma unroll
                for (int rr = 0; rr < 2; rr++) {
                    int n = mg * 32 + mt * 16 + g + rr * 8;
                    *(float2*)&ob[n * 192 + col0] =
                        make_float2(acc[mt][nt][rr * 2 + 0] + pb0,
                                    acc[mt][nt][rr * 2 + 1] + pb1);
                }
            }
        }
    }
}

// ---------------------------------------------------------------------------
extern "C" void kernel_launch(void* const* d_in, const int* in_sizes, int n_in,
                              void* d_out, int out_size)
{
    const float* x           = (const float*)d_in[0];
    const float* mask        = (const float*)d_in[1];
    const float* qkv_w       = (const float*)d_in[2];
    const float* q_bias      = (const float*)d_in[3];
    const float* v_bias      = (const float*)d_in[4];
    const float* logit_scale = (const float*)d_in[5];
    const float* cpb_w1      = (const float*)d_in[6];
    const float* cpb_b1      = (const float*)d_in[7];
    const float* cpb_w2      = (const float*)d_in[8];
    const float* proj_w      = (const float*)d_in[9];
    const float* proj_b      = (const float*)d_in[10];
    float* out = (float*)d_out;

    cudaFuncSetAttribute(win_attn_kernel,
                         cudaFuncAttributeMaxDynamicSharedMemorySize, SMEM_BYTES);

    prep_w_kernel<<<(QKV_TBL + PRJ_TBL + 255) / 256, 256>>>(qkv_w, proj_w);
    cpb_kernel<<<1, 256>>>(cpb_w1, cpb_b1, cpb_w2);
    bm_kernel<<<NW * NH, 256>>>(mask);
    win_attn_kernel<<<B_TOT, NTHREADS, SMEM_BYTES>>>(
        x, q_bias, v_bias, logit_scale, proj_b, out);
}

// round 16
// speedup vs baseline: 1.1342x; 1.1342x over previous
#include <cuda_runtime.h>
#include <math.h>
#include <stdint.h>

#define B_TOT   4096
#define NSEQ    64
#define CDIM    192
#define NH      6
#define NW      64
#define CPBH    512
#define NTHREADS 384

// Shared memory (32-bit words), all XOR-swizzled, no padding:
//  sxb : u32[64][96] bf16-value pairs of x / attn-out, pairidx ^ ((row&7)<<2)
//  sal : u32[64][96] bf16-lo  pairs of x / attn-out,   pairidx ^ ((row&7)<<2)
//  squ/sku : u32[6*64][32] dual-bf16 q/k pairs (norm-scaled):
//            value pair pi at (pi ^ swg), lo pair at ((16|pi) ^ swg), swg=(row&7)<<2
//  sv    : f32[6*64][32], col ^ ((row&7)<<2)   (conflict-free PV loads)
#define SXB_OFF 0
#define SAL_OFF (SXB_OFF + 64*96)
#define SQ_OFF  (SAL_OFF + 64*96)
#define SK_OFF  (SQ_OFF + NH*64*32)
#define SV_OFF  (SK_OFF + NH*64*32)
#define SSC_OFF (SV_OFF + NH*64*32)
#define SMEM_WORDS (SSC_OFF + 8)
#define SMEM_BYTES (SMEM_WORDS * 4)

__device__ float g_rpb[225 * NH];                       // raw CPB MLP output
__device__ float g_bm[(size_t)NW * NH * NSEQ * NSEQ];   // 16*sigmoid(rpb)+mask

// Weight tables: (ng, ks16 0..11, nt, lane) -> uint4(bbf0, bbf1, blo0, blo1)
#define QKV_TBL (6*12*12*32)
#define PRJ_TBL (6*12*4*32)
__device__ uint4 g_wq[QKV_TBL];
__device__ uint4 g_wp[PRJ_TBL];

__device__ __forceinline__ uint32_t packbf(float hi, float lo) {
    uint32_t r; asm("cvt.rn.bf16x2.f32 %0, %1, %2;" : "=r"(r) : "f"(hi), "f"(lo)); return r;
}
__device__ __forceinline__ float bflo(uint32_t u) { return __uint_as_float(u << 16); }
__device__ __forceinline__ float bfhi(uint32_t u) { return __uint_as_float(u & 0xffff0000u); }
__device__ __forceinline__ void mma16bf(float* d, const uint32_t* a, uint32_t b0, uint32_t b1) {
    asm volatile("mma.sync.aligned.m16n8k16.row.col.f32.bf16.bf16.f32 "
                 "{%0,%1,%2,%3},{%4,%5,%6,%7},{%8,%9},{%0,%1,%2,%3};"
                 : "+f"(d[0]), "+f"(d[1]), "+f"(d[2]), "+f"(d[3])
                 : "r"(a[0]), "r"(a[1]), "r"(a[2]), "r"(a[3]), "r"(b0), "r"(b1));
}

// ---------------------------------------------------------------------------
// Kernel 0: weight tables in dual-bf16 fragment order (per k16 step).
// ---------------------------------------------------------------------------
__global__ void prep_w_kernel(const float* __restrict__ qkv_w,
                              const float* __restrict__ proj_w)
{
    int i = blockIdx.x * blockDim.x + threadIdx.x;
    const float* w; uint4* dst; int NT, idx;
    if (i < QKV_TBL)                { w = qkv_w;  dst = g_wq; NT = 12; idx = i; }
    else if (i < QKV_TBL + PRJ_TBL) { w = proj_w; dst = g_wp; NT = 4;  idx = i - QKV_TBL; }
    else return;

    int lane = idx & 31, r = idx >> 5;
    int nt = r % NT; r /= NT;
    int ks = r % 12; int ng = r / 12;
    int g = lane >> 2, qd = lane & 3;
    int col = ng * (NT * 8) + nt * 8 + g;
    const float* wr = &w[col * 192 + ks * 16];

    float e0 = wr[2 * qd],     e1 = wr[2 * qd + 1];
    float e8 = wr[2 * qd + 8], e9 = wr[2 * qd + 9];
    uint32_t b0 = packbf(e1, e0);
    uint32_t b1 = packbf(e9, e8);
    uint32_t l0 = packbf(e1 - bfhi(b0), e0 - bflo(b0));
    uint32_t l1 = packbf(e9 - bfhi(b1), e8 - bflo(b1));
    dst[idx] = make_uint4(b0, b1, l0, l1);
}

// ---------------------------------------------------------------------------
// Kernel 1: CPB MLP, parallel — one block per table entry, 32 lanes per head.
// ---------------------------------------------------------------------------
__global__ void cpb_kernel(const float* __restrict__ w1,
                           const float* __restrict__ b1,
                           const float* __restrict__ w2)
{
    int te = blockIdx.x;               // 0..224
    int h = threadIdx.x >> 5;          // 0..5
    int lane = threadIdx.x & 31;
    int i = te / 15, j = te % 15;
    const float inv_log2_8 = 1.0f / 3.0f;
    float cy = (float)(i - 7) * (8.0f / 7.0f);
    float cx = (float)(j - 7) * (8.0f / 7.0f);
    cy = copysignf(log2f(fabsf(cy) + 1.0f), cy) * inv_log2_8;
    cx = copysignf(log2f(fabsf(cx) + 1.0f), cx) * inv_log2_8;

    float acc = 0.0f;
    for (int k = lane; k < CPBH; k += 32) {
        float hm = fmaxf(cy * w1[2 * k] + cx * w1[2 * k + 1] + b1[k], 0.0f);
        acc += hm * w2[h * CPBH + k];
    }
    #pragma unroll
    for (int off = 16; off; off >>= 1)
        acc += __shfl_xor_sync(0xffffffffu, acc, off);
    if (lane == 0) g_rpb[te * NH + h] = acc;
}

// ---------------------------------------------------------------------------
// Kernel 1b: combined 16*sigmoid(bias) + mask table.
// ---------------------------------------------------------------------------
__global__ void bm_kernel(const float* __restrict__ mask)
{
    int blk = blockIdx.x;            // widx*NH + h
    int widx = blk / NH, h = blk % NH;
    const float* mrow = mask + (size_t)widx * NSEQ * NSEQ;
    float* dst = g_bm + (size_t)blk * NSEQ * NSEQ;
    for (int e = threadIdx.x; e < NSEQ * NSEQ; e += 256) {
        int i = e >> 6, j = e & 63;
        int dy = (i >> 3) - (j >> 3) + 7;
        int dx = (i & 7) - (j & 7) + 7;
        float v = g_rpb[(dy * 15 + dx) * NH + h];
        dst[e] = 16.0f / (1.0f + expf(-v)) + mrow[e];
    }
}

// ---------------------------------------------------------------------------
__global__ __launch_bounds__(NTHREADS)
void win_attn_kernel(const float* __restrict__ x,
                     const float* __restrict__ q_bias,
                     const float* __restrict__ v_bias,
                     const float* __restrict__ logit_scale,
                     const float* __restrict__ proj_b,
                     float* __restrict__ out)
{
    extern __shared__ float sm[];
    uint32_t* sxb = (uint32_t*)(sm + SXB_OFF);
    uint32_t* sal = (uint32_t*)(sm + SAL_OFF);
    uint32_t* squ = (uint32_t*)(sm + SQ_OFF);
    uint32_t* sku = (uint32_t*)(sm + SK_OFF);
    float*    sv  = sm + SV_OFF;
    float*    sscale = sm + SSC_OFF;

    const int t = threadIdx.x;
    const int b = blockIdx.x;
    const int widx = b & (NW - 1);
    const float* xb = x + (size_t)b * NSEQ * CDIM;

    const int w    = t >> 5;
    const int lane = t & 31;
    const int g    = lane >> 2;
    const int qd   = lane & 3;
    const int swg  = g << 2;

    // -------- load x as dual-bf16 pairs (swizzled) --------
    for (int idx = t; idx < NSEQ * CDIM / 4; idx += NTHREADS) {
        float4 v4 = ((const float4*)xb)[idx];
        int n = (idx * 4) / CDIM;
        int p = ((idx * 4) % CDIM) >> 1;     // even pair index
        int sw = (n & 7) << 2;
        uint32_t b0 = packbf(v4.y, v4.x);
        uint32_t b1 = packbf(v4.w, v4.z);
        uint32_t l0 = packbf(v4.y - bfhi(b0), v4.x - bflo(b0));
        uint32_t l1 = packbf(v4.w - bfhi(b1), v4.z - bflo(b1));
        *(uint2*)&sxb[n * 96 + (p ^ sw)] = make_uint2(b0, b1);
        *(uint2*)&sal[n * 96 + (p ^ sw)] = make_uint2(l0, l1);
    }
    if (t < NH) sscale[t] = __expf(fminf(logit_scale[t], 4.60517019f)); // ln(100)
    __syncthreads();

    // ============ Phase 1: QKV GEMM (dual-bf16, 3 mma per k16) ============
    {
        const int mg = w & 1;
        const int ng = w >> 1;

        float acc[2][12][4];
        #pragma unroll
        for (int a = 0; a < 2; a++)
            #pragma unroll
            for (int nt = 0; nt < 12; nt++)
                #pragma unroll
                for (int e = 0; e < 4; e++) acc[a][nt][e] = 0.0f;

        const uint4* wtab = &g_wq[(ng * 12 * 12) * 32 + lane];

        #pragma unroll 2
        for (int ks = 0; ks < 12; ks++) {
            int c0 = 8 * ks;
            int i0 = (c0 + qd) ^ swg, i1 = (c0 + 4 + qd) ^ swg;
            uint32_t ab[2][4], al[2][4];
            #pragma unroll
            for (int mt = 0; mt < 2; mt++) {
                int r0 = mg * 32 + mt * 16 + g;
                const uint32_t* B0 = &sxb[r0 * 96];
                const uint32_t* B8 = B0 + 8 * 96;
                const uint32_t* L0 = &sal[r0 * 96];
                const uint32_t* L8 = L0 + 8 * 96;
                ab[mt][0] = B0[i0]; ab[mt][1] = B8[i0];
                ab[mt][2] = B0[i1]; ab[mt][3] = B8[i1];
                al[mt][0] = L0[i0]; al[mt][1] = L8[i0];
                al[mt][2] = L0[i1]; al[mt][3] = L8[i1];
            }
            const uint4* wrow = wtab + (ks * 12) * 32;
            #pragma unroll
            for (int nt = 0; nt < 12; nt++) {
                uint4 bb = wrow[nt * 32];
                #pragma unroll
                for (int mt = 0; mt < 2; mt++) {
                    mma16bf(acc[mt][nt], ab[mt], bb.x, bb.y);
                    mma16bf(acc[mt][nt], al[mt], bb.x, bb.y);
                    mma16bf(acc[mt][nt], ab[mt], bb.z, bb.w);
                }
            }
        }

        // ---- norms (q,k) then scatter with folded scales ----
        const int s = ng >> 1;   // 0=q, 1=k, 2=v
        float inv[2][2][3];
        if (s < 2) {
            float ssq[2][2][3];
            #pragma unroll
            for (int a = 0; a < 2; a++)
                #pragma unroll
                for (int c = 0; c < 2; c++)
                    #pragma unroll
                    for (int hh = 0; hh < 3; hh++) ssq[a][c][hh] = 0.0f;
            #pragma unroll
            for (int mt = 0; mt < 2; mt++)
                #pragma unroll
                for (int nt = 0; nt < 12; nt++) {
                    int rem = ng * 96 + nt * 8 + qd * 2 - s * 192;
                    #pragma unroll
                    for (int rr = 0; rr < 2; rr++) {
                        float v0 = acc[mt][nt][rr * 2 + 0];
                        float v1 = acc[mt][nt][rr * 2 + 1];
                        if (s == 0) { v0 += q_bias[rem]; v1 += q_bias[rem + 1]; }
                        ssq[mt][rr][nt >> 2] += v0 * v0 + v1 * v1;
                    }
                }
            #pragma unroll
            for (int mt = 0; mt < 2; mt++)
                #pragma unroll
                for (int rr = 0; rr < 2; rr++)
                    #pragma unroll
                    for (int hs = 0; hs < 3; hs++) {
                        float tot = ssq[mt][rr][hs];
                        tot += __shfl_xor_sync(0xffffffffu, tot, 1);
                        tot += __shfl_xor_sync(0xffffffffu, tot, 2);
                        float sc = (s == 0) ? sscale[(ng & 1) * 3 + hs] : 1.0f;
                        inv[mt][rr][hs] = sc / fmaxf(sqrtf(tot), 1e-12f);
                    }
        }

        #pragma unroll
        for (int mt = 0; mt < 2; mt++) {
            #pragma unroll
            for (int nt = 0; nt < 12; nt++) {
                int rem = ng * 96 + nt * 8 + qd * 2 - s * 192;
                int h = rem >> 5, d = rem & 31;
                int pi = d >> 1;
                #pragma unroll
                for (int rr = 0; rr < 2; rr++) {
                    int n = mg * 32 + mt * 16 + g + rr * 8;
                    float v0 = acc[mt][nt][rr * 2 + 0];
                    float v1 = acc[mt][nt][rr * 2 + 1];
                    if (s < 2) {
                        float iv = inv[mt][rr][nt >> 2];
                        float w0, w1;
                        if (s == 0) { w0 = (v0 + q_bias[rem]) * iv; w1 = (v1 + q_bias[rem + 1]) * iv; }
                        else        { w0 = v0 * iv; w1 = v1 * iv; }
                        uint32_t ub = packbf(w1, w0);
                        uint32_t ul = packbf(w1 - bfhi(ub), w0 - bflo(ub));
                        uint32_t* dstp = (s == 0) ? squ : sku;
                        int row = h * 64 + n;
                        dstp[row * 32 + (pi ^ swg)] = ub;
                        dstp[row * 32 + ((16 | pi) ^ swg)] = ul;
                    } else {
                        // sv swizzle: col ^ ((n&7)<<2); n&7 == g here
                        *(float2*)&sv[(h * 64 + n) * 32 + (d ^ swg)] =
                            make_float2(v0 + v_bias[rem], v1 + v_bias[rem + 1]);
                    }
                }
            }
        }
    }
    __syncthreads();

    // ============ Phase 2: attention (dual-bf16 S, dual-bf16 PV) ============
    {
        const int h  = w >> 1;
        const int m0 = (w & 1) * 32;

        float p[2][8][4];
        #pragma unroll
        for (int mt = 0; mt < 2; mt++)
            #pragma unroll
            for (int nt = 0; nt < 8; nt++)
                #pragma unroll
                for (int e = 0; e < 4; e++) p[mt][nt][e] = 0.0f;

        // ---- preload all q fragments (value + lo) for both k16 halves ----
        uint32_t aqb[2][2][4], aql[2][2][4];   // [u][mt][4]
        #pragma unroll
        for (int u = 0; u < 2; u++) {
            int c0 = (8 * u + qd) ^ swg;
            int c1 = (8 * u + 4 + qd) ^ swg;
            int c2 = (16 | (8 * u + qd)) ^ swg;
            int c3 = (16 | (8 * u + 4 + qd)) ^ swg;
            #pragma unroll
            for (int mt = 0; mt < 2; mt++) {
                const uint32_t* Q0 = &squ[(h * 64 + m0 + mt * 16 + g) * 32];
                const uint32_t* Q8 = Q0 + 8 * 32;
                aqb[u][mt][0] = Q0[c0]; aqb[u][mt][1] = Q8[c0];
                aqb[u][mt][2] = Q0[c1]; aqb[u][mt][3] = Q8[c1];
                aql[u][mt][0] = Q0[c2]; aql[u][mt][1] = Q8[c2];
                aql[u][mt][2] = Q0[c3]; aql[u][mt][3] = Q8[c3];
            }
        }

        #pragma unroll
        for (int u = 0; u < 2; u++) {
            int c0 = (8 * u + qd) ^ swg;
            int c1 = (8 * u + 4 + qd) ^ swg;
            int c2 = (16 | (8 * u + qd)) ^ swg;
            int c3 = (16 | (8 * u + 4 + qd)) ^ swg;
            #pragma unroll
            for (int nt = 0; nt < 8; nt++) {
                const uint32_t* K0 = &sku[(h * 64 + nt * 8 + g) * 32];
                uint32_t kb0 = K0[c0], kb1 = K0[c1];
                uint32_t kl0 = K0[c2], kl1 = K0[c3];
                #pragma unroll
                for (int mt = 0; mt < 2; mt++) {
                    mma16bf(p[mt][nt], aqb[u][mt], kb0, kb1);
                    mma16bf(p[mt][nt], aql[u][mt], kb0, kb1);
                    mma16bf(p[mt][nt], aqb[u][mt], kl0, kl1);
                }
            }
        }

        // ---- bias+mask, softmax ----
        const float* bmb = &g_bm[((size_t)widx * NH + h) * NSEQ * NSEQ];
        float rsn[2][2];
        #pragma unroll
        for (int mt = 0; mt < 2; mt++) {
            #pragma unroll
            for (int r2 = 0; r2 < 2; r2++) {
                int row = m0 + mt * 16 + g + 8 * r2;
                const float* bmr = bmb + row * 64 + qd * 2;
                float mx = -1e30f;
                #pragma unroll
                for (int nt = 0; nt < 8; nt++) {
                    float2 bmv = *(const float2*)&bmr[nt * 8];
                    p[mt][nt][r2 * 2 + 0] += bmv.x;
                    p[mt][nt][r2 * 2 + 1] += bmv.y;
                    mx = fmaxf(mx, fmaxf(p[mt][nt][r2 * 2], p[mt][nt][r2 * 2 + 1]));
                }
                mx = fmaxf(mx, __shfl_xor_sync(0xffffffffu, mx, 1));
                mx = fmaxf(mx, __shfl_xor_sync(0xffffffffu, mx, 2));
                float sum = 0.0f;
                #pragma unroll
                for (int nt = 0; nt < 8; nt++) {
                    float e0 = __expf(p[mt][nt][r2 * 2 + 0] - mx);
                    float e1 = __expf(p[mt][nt][r2 * 2 + 1] - mx);
                    p[mt][nt][r2 * 2 + 0] = e0;
                    p[mt][nt][r2 * 2 + 1] = e1;
                    sum += e0 + e1;
                }
                sum += __shfl_xor_sync(0xffffffffu, sum, 1);
                sum += __shfl_xor_sync(0xffffffffu, sum, 2);
                rsn[mt][r2] = 1.0f / sum;
            }
        }

        // ---- PV: dual-bf16 mma, P packed directly from S accumulators ----
        float o[2][4][4];
        #pragma unroll
        for (int mt = 0; mt < 2; mt++)
            #pragma unroll
            for (int nt = 0; nt < 4; nt++)
                #pragma unroll
                for (int e = 0; e < 4; e++) o[mt][nt][e] = 0.0f;

        #pragma unroll
        for (int u = 0; u < 4; u++) {
            uint32_t Ab[2][4], Al[2][4];
            #pragma unroll
            for (int mt = 0; mt < 2; mt++) {
                float p00 = p[mt][2*u][0],   p01 = p[mt][2*u][1];
                float p02 = p[mt][2*u][2],   p03 = p[mt][2*u][3];
                float p10 = p[mt][2*u+1][0], p11 = p[mt][2*u+1][1];
                float p12 = p[mt][2*u+1][2], p13 = p[mt][2*u+1][3];
                Ab[mt][0] = packbf(p01, p00);
                Ab[mt][1] = packbf(p03, p02);
                Ab[mt][2] = packbf(p11, p10);
                Ab[mt][3] = packbf(p13, p12);
                Al[mt][0] = packbf(p01 - bfhi(Ab[mt][0]), p00 - bflo(Ab[mt][0]));
                Al[mt][1] = packbf(p03 - bfhi(Ab[mt][1]), p02 - bflo(Ab[mt][1]));
                Al[mt][2] = packbf(p11 - bfhi(Ab[mt][2]), p10 - bflo(Ab[mt][2]));
                Al[mt][3] = packbf(p13 - bfhi(Ab[mt][3]), p12 - bflo(Ab[mt][3]));
            }
            int t0 = 16 * u + 2 * qd;
            int t1 = t0 + 8;
            #pragma unroll
            for (int nt = 0; nt < 4; nt++) {
                int d = nt * 8 + g;
                float v00 = sv[(h * 64 + t0) * 32     + (d ^ ((t0 & 7) << 2))];
                float v01 = sv[(h * 64 + t0 + 1) * 32 + (d ^ (((t0 + 1) & 7) << 2))];
                float v10 = sv[(h * 64 + t1) * 32     + (d ^ ((t1 & 7) << 2))];
                float v11 = sv[(h * 64 + t1 + 1) * 32 + (d ^ (((t1 + 1) & 7) << 2))];
                uint32_t B0 = packbf(v01, v00);
                uint32_t B1 = packbf(v11, v10);
                uint32_t L0 = packbf(v01 - bfhi(B0), v00 - bflo(B0));
                uint32_t L1 = packbf(v11 - bfhi(B1), v10 - bflo(B1));
                #pragma unroll
                for (int mt = 0; mt < 2; mt++) {
                    mma16bf(o[mt][nt], Ab[mt], B0, B1);
                    mma16bf(o[mt][nt], Al[mt], B0, B1);
                    mma16bf(o[mt][nt], Ab[mt], L0, L1);
                }
            }
        }

        // ---- write attn output (normalized) as dual-bf16 pairs ----
        #pragma unroll
        for (int mt = 0; mt < 2; mt++) {
            #pragma unroll
            for (int nt = 0; nt < 4; nt++) {
                int pidx = h * 16 + nt * 4 + qd;       // pair index of col0
                #pragma unroll
                for (int r2 = 0; r2 < 2; r2++) {
                    int row = m0 + mt * 16 + g + 8 * r2;
                    float rs = rsn[mt][r2];
                    float o0 = o[mt][nt][r2 * 2 + 0] * rs;
                    float o1 = o[mt][nt][r2 * 2 + 1] * rs;
                    uint32_t ob = packbf(o1, o0);
                    uint32_t ol = packbf(o1 - bfhi(ob), o0 - bflo(ob));
                    sxb[row * 96 + (pidx ^ swg)] = ob;
                    sal[row * 96 + (pidx ^ swg)] = ol;
                }
            }
        }
    }
    __syncthreads();

    // ============ Phase 3: proj GEMM (dual-bf16, 3 mma per k16) ============
    {
        const int mg = w & 1;
        const int ng = w >> 1;

        float acc[2][4][4];
        #pragma unroll
        for (int a = 0; a < 2; a++)
            #pragma unroll
            for (int nt = 0; nt < 4; nt++)
                #pragma unroll
                for (int e = 0; e < 4; e++) acc[a][nt][e] = 0.0f;

        const uint4* wtab = &g_wp[(ng * 12 * 4) * 32 + lane];

        #pragma unroll 4
        for (int ks = 0; ks < 12; ks++) {
            int c0 = 8 * ks;
            int i0 = (c0 + qd) ^ swg, i1 = (c0 + 4 + qd) ^ swg;
            uint32_t ab[2][4], al[2][4];
            #pragma unroll
            for (int mt = 0; mt < 2; mt++) {
                int r0 = mg * 32 + mt * 16 + g;
                const uint32_t* B0 = &sxb[r0 * 96];
                const uint32_t* B8 = B0 + 8 * 96;
                const uint32_t* L0 = &sal[r0 * 96];
                const uint32_t* L8 = L0 + 8 * 96;
                ab[mt][0] = B0[i0]; ab[mt][1] = B8[i0];
                ab[mt][2] = B0[i1]; ab[mt][3] = B8[i1];
                al[mt][0] = L0[i0]; al[mt][1] = L8[i0];
                al[mt][2] = L0[i1]; al[mt][3] = L8[i1];
            }
            const uint4* wrow = wtab + (ks * 4) * 32;
            #pragma unroll
            for (int nt = 0; nt < 4; nt++) {
                uint4 bb = wrow[nt * 32];
                #pragma unroll
                for (int mt = 0; mt < 2; mt++) {
                    mma16bf(acc[mt][nt], ab[mt], bb.x, bb.y);
                    mma16bf(acc[mt][nt], al[mt], bb.x, bb.y);
                    mma16bf(acc[mt][nt], ab[mt], bb.z, bb.w);
                }
            }
        }

        float* ob = out + (size_t)b * NSEQ * CDIM;
        #pragma unroll
        for (int mt = 0; mt < 2; mt++) {
            #pragma unroll
            for (int nt = 0; nt < 4; nt++) {
                int col0 = ng * 32 + nt * 8 + qd * 2;
                float pb0 = proj_b[col0], pb1 = proj_b[col0 + 1];
                #pragma unroll
                for (int rr = 0; rr < 2; rr++) {
                    int n = mg * 32 + mt * 16 + g + rr * 8;
                    *(float2*)&ob[n * 192 + col0] =
                        make_float2(acc[mt][nt][rr * 2 + 0] + pb0,
                                    acc[mt][nt][rr * 2 + 1] + pb1);
                }
            }
        }
    }
}

// ---------------------------------------------------------------------------
extern "C" void kernel_launch(void* const* d_in, const int* in_sizes, int n_in,
                              void* d_out, int out_size)
{
    const float* x           = (const float*)d_in[0];
    const float* mask        = (const float*)d_in[1];
    const float* qkv_w       = (const float*)d_in[2];
    const float* q_bias      = (const float*)d_in[3];
    const float* v_bias      = (const float*)d_in[4];
    const float* logit_scale = (const float*)d_in[5];
    const float* cpb_w1      = (const float*)d_in[6];
    const float* cpb_b1      = (const float*)d_in[7];
    const float* cpb_w2      = (const float*)d_in[8];
    const float* proj_w      = (const float*)d_in[9];
    const float* proj_b      = (const float*)d_in[10];
    float* out = (float*)d_out;

    cudaFuncSetAttribute(win_attn_kernel,
                         cudaFuncAttributeMaxDynamicSharedMemorySize, SMEM_BYTES);

    prep_w_kernel<<<(QKV_TBL + PRJ_TBL + 255) / 256, 256>>>(qkv_w, proj_w);
    cpb_kernel<<<225, 192>>>(cpb_w1, cpb_b1, cpb_w2);
    bm_kernel<<<NW * NH, 256>>>(mask);
    win_attn_kernel<<<B_TOT, NTHREADS, SMEM_BYTES>>>(
        x, q_bias, v_bias, logit_scale, proj_b, out);
}